// round 10
// baseline (speedup 1.0000x reference)
#include <cuda_runtime.h>
#include <cstdint>

// Problem constants
#define BB 32
#define II 4096
#define VV 512
#define VTILE 128          // v per CTA (M)
#define CTA_I 32           // i per CTA -> K = 256
#define NCHUNK (II/CTA_I)  // 128 k-splits
#define NRED 8
#define NTHREADS 256
#define S528 528           // Bhl b-row stride in floats (512 data + 16 pad; %32==16)

__device__ float g_part[NCHUNK][BB * VV];   // split-K partials (8 MB)
__device__ float g_red[NRED][BB * VV];      // second-stage partials

// tf32 split: hi = top 19 bits (valid tf32); lo = masked remainder
__device__ __forceinline__ uint32_t tf32_hi(float f) {
    return __float_as_uint(f) & 0xFFFFE000u;
}
__device__ __forceinline__ uint32_t tf32_lo(float f, uint32_t hi) {
    return __float_as_uint(f - __uint_as_float(hi)) & 0xFFFFE000u;
}

__device__ __forceinline__ void mma_tf32(float* c, const uint32_t* a,
                                         const uint32_t* b) {
    asm volatile(
        "mma.sync.aligned.m16n8k8.row.col.f32.tf32.tf32.f32 "
        "{%0,%1,%2,%3}, {%4,%5,%6,%7}, {%8,%9}, {%0,%1,%2,%3};"
        : "+f"(c[0]), "+f"(c[1]), "+f"(c[2]), "+f"(c[3])
        : "r"(a[0]), "r"(a[1]), "r"(a[2]), "r"(a[3]), "r"(b[0]), "r"(b[1]));
}

// D[v_local, b] = sum_k A[v_local,k]*B[k,b].
// A (=W) streamed straight from GMEM (zero reuse; no smem, no barriers).
// B (=x) split into tf32 hi/lo ONCE at staging; mainloop reads one LDS.128
// per fragment pair: Bhl[b][il][t] = {bh(k), bh(k+4), bl(k), bl(k+4)}.
__global__ void __launch_bounds__(NTHREADS)
caps_mma_kernel(const float4* __restrict__ x4, const float* __restrict__ w) {
    __shared__ float Bhl[BB * S528];   // 67.6 KB

    const int tid  = threadIdx.x;
    const int wrp  = tid >> 5;        // warp 0..7 -> m rows [wrp*16, wrp*16+16)
    const int lane = tid & 31;
    const int g    = lane >> 2;       // groupID 0..7
    const int t    = lane & 3;        // threadID-in-group 0..3
    const int v0   = blockIdx.x * VTILE;
    const int i0   = blockIdx.y * CTA_I;

    // ---- stage + split B once: 1024 (b,il) rows, 4 per thread ----
    #pragma unroll
    for (int j = 0; j < 4; ++j) {
        const int p  = tid + j * NTHREADS;   // 0..1023
        const int b  = p >> 5;
        const int il = p & 31;
        const size_t f4 = (size_t)b * 8192 + (size_t)(i0 + il) * 2;
        float4 xa = x4[f4], xb = x4[f4 + 1];
        float f[8] = { xa.x, xa.y, xa.z, xa.w, xb.x, xb.y, xb.z, xb.w };
        uint32_t hi[8], lo[8];
        #pragma unroll
        for (int k = 0; k < 8; ++k) {
            hi[k] = tf32_hi(f[k]);
            lo[k] = tf32_lo(f[k], hi[k]);
        }
        float* dst = &Bhl[b * S528 + il * 16];
        #pragma unroll
        for (int tt = 0; tt < 4; ++tt)
            *(float4*)(dst + tt * 4) =
                make_float4(__uint_as_float(hi[tt]), __uint_as_float(hi[tt + 4]),
                            __uint_as_float(lo[tt]), __uint_as_float(lo[tt + 4]));
    }

    float c[4][4];
    #pragma unroll
    for (int nt = 0; nt < 4; ++nt)
        #pragma unroll
        for (int j = 0; j < 4; ++j) c[nt][j] = 0.f;

    const int row = wrp * 16 + g;                             // A row (v_local)
    const float* wp = w + ((size_t)i0 * 512 + v0 + row) * 8;  // W[i0][v0+row][0]

    __syncthreads();   // the only barrier: split-B resident

    // ---- mainloop: 32 i's, K=8 each; no syncs, warps fully decoupled ----
    #pragma unroll 8
    for (int il = 0; il < CTA_I; ++il) {
        // A fragment direct from GMEM: rows row, row+8; cols t, t+4 (d-dim)
        const float* ap = wp + (size_t)il * 4096;   // W[i0+il][v0+row][0]
        float af[4] = { ap[t], ap[64 + t], ap[t + 4], ap[64 + t + 4] };
        uint32_t ah[4], al[4];
        #pragma unroll
        for (int j = 0; j < 4; ++j) {
            ah[j] = tf32_hi(af[j]);
            al[j] = tf32_lo(af[j], ah[j]);
        }
        #pragma unroll
        for (int nt = 0; nt < 4; ++nt) {
            // one conflict-free LDS.128: {bh0, bh1, bl0, bl1}
            const float4 bq =
                *(const float4*)&Bhl[(nt * 8 + g) * S528 + il * 16 + t * 4];
            uint32_t bh[2] = { __float_as_uint(bq.x), __float_as_uint(bq.y) };
            uint32_t bl[2] = { __float_as_uint(bq.z), __float_as_uint(bq.w) };
            mma_tf32(c[nt], ah, bh);
            mma_tf32(c[nt], ah, bl);
            mma_tf32(c[nt], al, bh);
        }
    }

    // ---- epilogue: scatter accumulators to split-K partials ----
    float* outp = &g_part[blockIdx.y][0];
    #pragma unroll
    for (int nt = 0; nt < 4; ++nt) {
        const int bc = nt * 8 + t * 2;
        outp[(size_t)bc * VV + v0 + row]           = c[nt][0];
        outp[(size_t)(bc + 1) * VV + v0 + row]     = c[nt][1];
        outp[(size_t)bc * VV + v0 + row + 8]       = c[nt][2];
        outp[(size_t)(bc + 1) * VV + v0 + row + 8] = c[nt][3];
    }
}

// First-stage reduction: 256 blocks, each folds 16 chunks for one b.
__global__ void __launch_bounds__(256)
caps_reduce_kernel() {
    const int b   = blockIdx.x;   // 0..31
    const int s   = blockIdx.y;   // 0..NRED-1
    const int tid = threadIdx.x;
    #pragma unroll
    for (int j = 0; j < 2; ++j) {
        const int v = tid + j * 256;
        float acc = 0.f;
        #pragma unroll
        for (int cc = 0; cc < NCHUNK / NRED; ++cc)
            acc += g_part[s * (NCHUNK / NRED) + cc][b * VV + v];
        g_red[s][b * VV + v] = acc;
    }
}

// Final: fold NRED partials, squash, write (t, outputs) — identical halves.
__global__ void __launch_bounds__(256)
caps_finish_kernel(float* __restrict__ out, int out_size) {
    const int b   = blockIdx.x;
    const int tid = threadIdx.x;
    __shared__ float red[256];

    float local[2];
    #pragma unroll
    for (int j = 0; j < 2; ++j) {
        const int v = tid + j * 256;
        float acc = 0.f;
        #pragma unroll
        for (int cc = 0; cc < NRED; ++cc) acc += g_red[cc][b * VV + v];
        local[j] = acc;
    }

    float sq = local[0] * local[0] + local[1] * local[1];
    red[tid] = sq;
    __syncthreads();
    for (int off = 128; off; off >>= 1) {
        if (tid < off) red[tid] += red[tid + off];
        __syncthreads();
    }
    const float total = red[0];
    const float scale = total / ((1.0f + total) * sqrtf(total));

    #pragma unroll
    for (int j = 0; j < 2; ++j) {
        const int v   = tid + j * 256;
        const float o = local[j] * scale;
        const int idx = b * VV + v;
        if (idx < out_size) out[idx] = o;                       // t
        if (idx + BB * VV < out_size) out[idx + BB * VV] = o;   // outputs
    }
}

extern "C" void kernel_launch(void* const* d_in, const int* in_sizes, int n_in,
                              void* d_out, int out_size) {
    const float4* x4 = (const float4*)d_in[0];  // x: [32, 4096, 8] fp32
    const float*  w  = (const float*)d_in[1];   // W: [1, 4096, 512, 8] fp32
    float* out = (float*)d_out;

    dim3 grid1(VV / VTILE, NCHUNK);  // (4, 128) = 512 CTAs
    caps_mma_kernel<<<grid1, NTHREADS>>>(x4, w);
    caps_reduce_kernel<<<dim3(BB, NRED), 256>>>();
    caps_finish_kernel<<<BB, 256>>>(out, out_size);
}

// round 11
// speedup vs baseline: 1.3393x; 1.3393x over previous
#include <cuda_runtime.h>
#include <cstdint>

// Problem constants
#define BB 32
#define II 4096
#define VV 512
#define VTILE 128          // v per CTA (M)
#define CTA_I 32           // i per CTA -> K = 256
#define NCHUNK (II/CTA_I)  // 128 k-splits
#define NRED 8
#define NTHREADS 256
#define BSTRIDE 260        // floats per B row (256 data + 4 pad): conflict-free

__device__ float g_part[NCHUNK][BB * VV];   // split-K partials (8 MB)
__device__ float g_red[NRED][BB * VV];      // second-stage partials

__device__ __forceinline__ void cp_async16(void* smem_dst, const void* gmem_src) {
    unsigned s = (unsigned)__cvta_generic_to_shared(smem_dst);
    asm volatile("cp.async.cg.shared.global [%0], [%1], 16;"
                 :: "r"(s), "l"(gmem_src));
}
__device__ __forceinline__ void cp_commit() {
    asm volatile("cp.async.commit_group;" ::: "memory");
}
__device__ __forceinline__ void cp_wait0() {
    asm volatile("cp.async.wait_group 0;" ::: "memory");
}

// fp32 -> tf32 with round-to-nearest (unbiased; rel err <= 2^-11)
__device__ __forceinline__ uint32_t f2tf(float f) {
    uint32_t r;
    asm("cvt.rna.tf32.f32 %0, %1;" : "=r"(r) : "f"(f));
    return r;
}

__device__ __forceinline__ void mma_tf32(float* c, const uint32_t* a,
                                         const uint32_t* b) {
    asm volatile(
        "mma.sync.aligned.m16n8k8.row.col.f32.tf32.tf32.f32 "
        "{%0,%1,%2,%3}, {%4,%5,%6,%7}, {%8,%9}, {%0,%1,%2,%3};"
        : "+f"(c[0]), "+f"(c[1]), "+f"(c[2]), "+f"(c[3])
        : "r"(a[0]), "r"(a[1]), "r"(a[2]), "r"(a[3]), "r"(b[0]), "r"(b[1]));
}

// D[v_local, b] = sum_k A[v_local,k]*B[k,b].  A (=W) streamed directly from
// GMEM (zero reuse -> no smem, no barriers); B (=x) staged once in smem.
// Single rounded-TF32 MMA per fragment (precision budget: 1e-3 >> ~3e-4).
__global__ void __launch_bounds__(NTHREADS)
caps_mma_kernel(const float4* __restrict__ x4, const float* __restrict__ w) {
    __shared__ float Bsm[BB * BSTRIDE];   // 32 x 260 floats = 33.3 KB

    const int tid  = threadIdx.x;
    const int wrp  = tid >> 5;        // warp 0..7 -> m rows [wrp*16, wrp*16+16)
    const int lane = tid & 31;
    const int g    = lane >> 2;       // groupID 0..7
    const int t    = lane & 3;        // threadID-in-group 0..3
    const int v0   = blockIdx.x * VTILE;
    const int i0   = blockIdx.y * CTA_I;

    // ---- stage B once: x[b][i0..i0+32][0..8] -> Bsm[b][k], k=(i-i0)*8+d ----
    #pragma unroll
    for (int j = 0; j < 8; ++j) {
        const int t4 = tid + j * NTHREADS;   // 0..2047
        const int b  = t4 >> 6;              // 64 float4 per b-row
        const int kq = t4 & 63;
        cp_async16(&Bsm[b * BSTRIDE + kq * 4],
                   &x4[(size_t)b * 8192 + (size_t)i0 * 2 + kq]);
    }
    cp_commit();

    float c[4][4];
    #pragma unroll
    for (int nt = 0; nt < 4; ++nt)
        #pragma unroll
        for (int j = 0; j < 4; ++j) c[nt][j] = 0.f;

    const int row = wrp * 16 + g;                         // A row (v_local)
    const float* wp = w + ((size_t)i0 * 512 + v0 + row) * 8;  // W[i0][v0+row][0]

    cp_wait0();
    __syncthreads();   // the only barrier: B resident

    // ---- mainloop: 32 i's, K=8 each; no syncs, warps fully decoupled ----
    #pragma unroll 8
    for (int il = 0; il < CTA_I; ++il) {
        // A fragment direct from GMEM: rows row, row+8; cols t, t+4 (d-dim)
        const float* ap = wp + (size_t)il * 4096;   // W[i0+il][v0+row][0]
        uint32_t a[4] = { f2tf(ap[t]), f2tf(ap[64 + t]),
                          f2tf(ap[t + 4]), f2tf(ap[64 + t + 4]) };
        #pragma unroll
        for (int nt = 0; nt < 4; ++nt) {
            // B fragment: col n = nt*8+g (b), rows k = il*8+t, +4
            const float* bp = &Bsm[(nt * 8 + g) * BSTRIDE + il * 8 + t];
            uint32_t b[2] = { f2tf(bp[0]), f2tf(bp[4]) };
            mma_tf32(c[nt], a, b);
        }
    }

    // ---- epilogue: scatter accumulators to split-K partials ----
    float* outp = &g_part[blockIdx.y][0];
    #pragma unroll
    for (int nt = 0; nt < 4; ++nt) {
        const int bc = nt * 8 + t * 2;
        outp[(size_t)bc * VV + v0 + row]           = c[nt][0];
        outp[(size_t)(bc + 1) * VV + v0 + row]     = c[nt][1];
        outp[(size_t)bc * VV + v0 + row + 8]       = c[nt][2];
        outp[(size_t)(bc + 1) * VV + v0 + row + 8] = c[nt][3];
    }
}

// First-stage reduction: 256 blocks, each folds 16 chunks for one b.
__global__ void __launch_bounds__(256)
caps_reduce_kernel() {
    const int b   = blockIdx.x;   // 0..31
    const int s   = blockIdx.y;   // 0..NRED-1
    const int tid = threadIdx.x;
    #pragma unroll
    for (int j = 0; j < 2; ++j) {
        const int v = tid + j * 256;
        float acc = 0.f;
        #pragma unroll
        for (int cc = 0; cc < NCHUNK / NRED; ++cc)
            acc += g_part[s * (NCHUNK / NRED) + cc][b * VV + v];
        g_red[s][b * VV + v] = acc;
    }
}

// Final: fold NRED partials, squash, write (t, outputs) — identical halves.
__global__ void __launch_bounds__(256)
caps_finish_kernel(float* __restrict__ out, int out_size) {
    const int b   = blockIdx.x;
    const int tid = threadIdx.x;
    __shared__ float red[256];

    float local[2];
    #pragma unroll
    for (int j = 0; j < 2; ++j) {
        const int v = tid + j * 256;
        float acc = 0.f;
        #pragma unroll
        for (int cc = 0; cc < NRED; ++cc) acc += g_red[cc][b * VV + v];
        local[j] = acc;
    }

    float sq = local[0] * local[0] + local[1] * local[1];
    red[tid] = sq;
    __syncthreads();
    for (int off = 128; off; off >>= 1) {
        if (tid < off) red[tid] += red[tid + off];
        __syncthreads();
    }
    const float total = red[0];
    const float scale = total / ((1.0f + total) * sqrtf(total));

    #pragma unroll
    for (int j = 0; j < 2; ++j) {
        const int v   = tid + j * 256;
        const float o = local[j] * scale;
        const int idx = b * VV + v;
        if (idx < out_size) out[idx] = o;                       // t
        if (idx + BB * VV < out_size) out[idx + BB * VV] = o;   // outputs
    }
}

extern "C" void kernel_launch(void* const* d_in, const int* in_sizes, int n_in,
                              void* d_out, int out_size) {
    const float4* x4 = (const float4*)d_in[0];  // x: [32, 4096, 8] fp32
    const float*  w  = (const float*)d_in[1];   // W: [1, 4096, 512, 8] fp32
    float* out = (float*)d_out;

    dim3 grid1(VV / VTILE, NCHUNK);  // (4, 128) = 512 CTAs
    caps_mma_kernel<<<grid1, NTHREADS>>>(x4, w);
    caps_reduce_kernel<<<dim3(BB, NRED), 256>>>();
    caps_finish_kernel<<<BB, 256>>>(out, out_size);
}